// round 4
// baseline (speedup 1.0000x reference)
#include <cuda_runtime.h>

// Problem constants
#define E_   16
#define KSEL 2
#define DIM  1024
#define FF   512
#define TOK  4096
#define TKN  (TOK * KSEL)   // 8192 (token, expert) slots

// GEMM tiling
#define BM 64
#define BN 64
#define BK 16

// ---------------- scratch (no allocations allowed -> device globals) ----------
__device__ int   g_is64;           // 1 if topk_indices is int64, 0 if int32
__device__ int   g_cnt[E_];
__device__ int   g_off[E_ + 1];
__device__ int   g_cur[E_];
__device__ int   g_tok[TKN];       // source token id per compacted slot
__device__ float g_wt[TKN];        // routing weight per compacted slot
__device__ float g_h[(size_t)TKN * FF];   // 16 MB intermediate activations

// ---------------- dtype sniff --------------------------------------------------
// Read index buffer as int32 words (safe for both dtypes: we touch only the
// first TKN words). int64-LE data => all odd words are zero high-halves.
// int32 data => odd words are expert ids in [0,16), not all zero (P~16^-4096).
__global__ void k_sniff(const int* __restrict__ w32) {
    __shared__ int acc;
    if (threadIdx.x == 0) acc = 0;
    __syncthreads();
    int o = 0;
    for (int i = threadIdx.x; i < TKN / 2; i += blockDim.x)
        o |= w32[2 * i + 1];
    atomicOr(&acc, o);
    __syncthreads();
    if (threadIdx.x == 0) {
        g_is64 = (acc == 0) ? 1 : 0;
        for (int e = 0; e < E_; e++) g_cnt[e] = 0;
    }
}

__device__ __forceinline__ int load_expert(const int* w32, int s) {
    // stride 2 words (int64) or 1 word (int32); low word is the value either way
    return g_is64 ? w32[2 * s] : w32[s];
}

// ---------------- zero output (no cudaMemsetAsync) -----------------------------
__global__ void k_zero_out(float4* __restrict__ out, int n4) {
    int i = blockIdx.x * blockDim.x + threadIdx.x;
    if (i < n4) out[i] = make_float4(0.f, 0.f, 0.f, 0.f);
}

// ---------------- dispatch -----------------------------------------------------
__global__ void k_count(const int* __restrict__ idx32) {
    int s = blockIdx.x * blockDim.x + threadIdx.x;
    if (s < TKN) {
        int e = load_expert(idx32, s) & (E_ - 1);
        atomicAdd(&g_cnt[e], 1);
    }
}

__global__ void k_scan() {
    int acc = 0;
    for (int e = 0; e < E_; e++) {
        g_off[e] = acc;
        g_cur[e] = acc;
        acc += g_cnt[e];
    }
    g_off[E_] = acc;
}

__global__ void k_scatter(const int* __restrict__ idx32,
                          const float* __restrict__ w) {
    int s = blockIdx.x * blockDim.x + threadIdx.x;
    if (s < TKN) {
        int e = load_expert(idx32, s) & (E_ - 1);
        int p = atomicAdd(&g_cur[e], 1);
        g_tok[p] = s / KSEL;
        g_wt[p]  = w[s];
    }
}

// ---------------- pass 1: h = silu(X Wg) * (X Wu), grouped by expert -----------
__global__ __launch_bounds__(256)
void k_gemm1(const float* __restrict__ x,
             const float* __restrict__ wg,
             const float* __restrict__ wu) {
    int e    = blockIdx.z;
    int base = g_off[e];
    int ne   = g_off[e + 1] - base;
    int m0   = blockIdx.y * BM;
    if (m0 >= ne) return;
    int n0 = blockIdx.x * BN;

    __shared__ float As[BK][BM];
    __shared__ float Bg[BK][BN];
    __shared__ float Bu[BK][BN];

    int tid = threadIdx.x;
    int tx  = tid & 15;       // n-direction (16 threads * 4 = 64)
    int ty  = tid >> 4;       // m-direction

    // A load mapping: 64 rows x 16 k, one float4 per thread
    int aRow = tid >> 2;
    int aCol = (tid & 3) * 4;
    const float* xrow = nullptr;
    if (m0 + aRow < ne) xrow = x + (size_t)g_tok[base + m0 + aRow] * DIM;

    // B load mapping: 16 k-rows x 64 n, one float4 per thread
    int bRow = tid >> 4;
    int bCol = (tid & 15) * 4;
    const float* wgp = wg + (size_t)e * DIM * FF;
    const float* wup = wu + (size_t)e * DIM * FF;

    float acc_g[4][4] = {};
    float acc_u[4][4] = {};

    for (int k0 = 0; k0 < DIM; k0 += BK) {
        float4 av = make_float4(0.f, 0.f, 0.f, 0.f);
        if (xrow) av = *reinterpret_cast<const float4*>(xrow + k0 + aCol);
        As[aCol + 0][aRow] = av.x;
        As[aCol + 1][aRow] = av.y;
        As[aCol + 2][aRow] = av.z;
        As[aCol + 3][aRow] = av.w;

        float4 gv = *reinterpret_cast<const float4*>(
            wgp + (size_t)(k0 + bRow) * FF + n0 + bCol);
        float4 uv = *reinterpret_cast<const float4*>(
            wup + (size_t)(k0 + bRow) * FF + n0 + bCol);
        *reinterpret_cast<float4*>(&Bg[bRow][bCol]) = gv;
        *reinterpret_cast<float4*>(&Bu[bRow][bCol]) = uv;
        __syncthreads();

#pragma unroll
        for (int k = 0; k < BK; k++) {
            float a[4], bgv[4], buv[4];
#pragma unroll
            for (int i = 0; i < 4; i++) a[i] = As[k][ty * 4 + i];
#pragma unroll
            for (int j = 0; j < 4; j++) {
                bgv[j] = Bg[k][tx * 4 + j];
                buv[j] = Bu[k][tx * 4 + j];
            }
#pragma unroll
            for (int i = 0; i < 4; i++)
#pragma unroll
                for (int j = 0; j < 4; j++) {
                    acc_g[i][j] += a[i] * bgv[j];
                    acc_u[i][j] += a[i] * buv[j];
                }
        }
        __syncthreads();
    }

#pragma unroll
    for (int i = 0; i < 4; i++) {
        int m = m0 + ty * 4 + i;
        if (m < ne) {
            float* hp = g_h + (size_t)(base + m) * FF + n0 + tx * 4;
#pragma unroll
            for (int j = 0; j < 4; j++) {
                float g = acc_g[i][j];
                float s = g / (1.f + __expf(-g));   // silu
                hp[j] = s * acc_u[i][j];
            }
        }
    }
}

// ---------------- pass 2: out[t] += w * (h Wd), grouped by expert --------------
__global__ __launch_bounds__(256)
void k_gemm2(const float* __restrict__ wd, float* __restrict__ out) {
    int e    = blockIdx.z;
    int base = g_off[e];
    int ne   = g_off[e + 1] - base;
    int m0   = blockIdx.y * BM;
    if (m0 >= ne) return;
    int n0 = blockIdx.x * BN;

    __shared__ float As[BK][BM];
    __shared__ float Bs[BK][BN];

    int tid = threadIdx.x;
    int tx  = tid & 15;
    int ty  = tid >> 4;

    int aRow = tid >> 2;
    int aCol = (tid & 3) * 4;
    const float* hrow = nullptr;
    if (m0 + aRow < ne) hrow = g_h + (size_t)(base + m0 + aRow) * FF;

    int bRow = tid >> 4;
    int bCol = (tid & 15) * 4;
    const float* wdp = wd + (size_t)e * FF * DIM;

    float acc[4][4] = {};

    for (int k0 = 0; k0 < FF; k0 += BK) {
        float4 av = make_float4(0.f, 0.f, 0.f, 0.f);
        if (hrow) av = *reinterpret_cast<const float4*>(hrow + k0 + aCol);
        As[aCol + 0][aRow] = av.x;
        As[aCol + 1][aRow] = av.y;
        As[aCol + 2][aRow] = av.z;
        As[aCol + 3][aRow] = av.w;

        float4 bv = *reinterpret_cast<const float4*>(
            wdp + (size_t)(k0 + bRow) * DIM + n0 + bCol);
        *reinterpret_cast<float4*>(&Bs[bRow][bCol]) = bv;
        __syncthreads();

#pragma unroll
        for (int k = 0; k < BK; k++) {
            float a[4], b[4];
#pragma unroll
            for (int i = 0; i < 4; i++) a[i] = As[k][ty * 4 + i];
#pragma unroll
            for (int j = 0; j < 4; j++) b[j] = Bs[k][tx * 4 + j];
#pragma unroll
            for (int i = 0; i < 4; i++)
#pragma unroll
                for (int j = 0; j < 4; j++) acc[i][j] += a[i] * b[j];
        }
        __syncthreads();
    }

#pragma unroll
    for (int i = 0; i < 4; i++) {
        int m = m0 + ty * 4 + i;
        if (m < ne) {
            int   t = g_tok[base + m];
            float w = g_wt[base + m];
            float* op = out + (size_t)t * DIM + n0 + tx * 4;
#pragma unroll
            for (int j = 0; j < 4; j++) {
                atomicAdd(&op[j], w * acc[i][j]);
            }
        }
    }
}

// ---------------- launch -------------------------------------------------------
extern "C" void kernel_launch(void* const* d_in, const int* in_sizes, int n_in,
                              void* d_out, int out_size) {
    const float* x     = (const float*)d_in[0];
    const int*   idx32 = (const int*)d_in[1];   // int32 words; dtype sniffed on device
    const float* w     = (const float*)d_in[2];
    const float* wg    = (const float*)d_in[3];
    const float* wu    = (const float*)d_in[4];
    const float* wd    = (const float*)d_in[5];
    float*       out   = (float*)d_out;

    int n4 = out_size / 4;
    k_zero_out<<<(n4 + 255) / 256, 256>>>((float4*)out, n4);

    k_sniff<<<1, 256>>>(idx32);
    k_count<<<(TKN + 255) / 256, 256>>>(idx32);
    k_scan<<<1, 1>>>();
    k_scatter<<<(TKN + 255) / 256, 256>>>(idx32, w);

    dim3 grid1(FF / BN, (TKN + BM - 1) / BM, E_);
    k_gemm1<<<grid1, 256>>>(x, wg, wu);

    dim3 grid2(DIM / BN, (TKN + BM - 1) / BM, E_);
    k_gemm2<<<grid2, 256>>>(wd, out);
}

// round 6
// speedup vs baseline: 1.0153x; 1.0153x over previous
#include <cuda_runtime.h>
#include <cuda_bf16.h>
#include <cstdint>

#define E_   16
#define KSEL 2
#define DIM  1024
#define FF   512
#define TOK  4096
#define TKN  (TOK * KSEL)
#define CAP  2048          // per-expert capacity (matches reference C)

// ---------------- device scratch ----------------------------------------------
__device__ int g_is64;
__device__ int g_cnt[E_];
__device__ int g_off[E_ + 1];
__device__ int g_cur[E_];
__device__ int g_tok[TKN];
__device__ int g_pos[TKN];          // flat slot -> compacted pos, -1 if dropped
__device__ __align__(16) __nv_bfloat16 g_xhi[(size_t)TOK * DIM];
__device__ __align__(16) __nv_bfloat16 g_xlo[(size_t)TOK * DIM];
__device__ __align__(16) __nv_bfloat16 g_wgThi[(size_t)E_ * FF * DIM];
__device__ __align__(16) __nv_bfloat16 g_wgTlo[(size_t)E_ * FF * DIM];
__device__ __align__(16) __nv_bfloat16 g_wuThi[(size_t)E_ * FF * DIM];
__device__ __align__(16) __nv_bfloat16 g_wuTlo[(size_t)E_ * FF * DIM];
__device__ __align__(16) __nv_bfloat16 g_wdThi[(size_t)E_ * DIM * FF];
__device__ __align__(16) __nv_bfloat16 g_wdTlo[(size_t)E_ * DIM * FF];
__device__ __align__(16) __nv_bfloat16 g_hhi[(size_t)TKN * FF];
__device__ __align__(16) __nv_bfloat16 g_hlo[(size_t)TKN * FF];
__device__ __align__(16) float g_y[(size_t)TKN * DIM];

// ---------------- helpers -------------------------------------------------------
__device__ __forceinline__ uint32_t smem_u32(const void* p) {
    uint32_t a;
    asm("{ .reg .u64 t; cvta.to.shared.u64 t, %1; cvt.u32.u64 %0, t; }" : "=r"(a) : "l"(p));
    return a;
}
__device__ __forceinline__ void cpa16(uint32_t sm, const void* g) {
    asm volatile("cp.async.ca.shared.global [%0], [%1], 16;" :: "r"(sm), "l"(g));
}
#define CPA_COMMIT() asm volatile("cp.async.commit_group;" ::: "memory")
#define CPA_WAIT0()  asm volatile("cp.async.wait_group 0;" ::: "memory")
#define CPA_WAIT1()  asm volatile("cp.async.wait_group 1;" ::: "memory")

__device__ __forceinline__ void ldm4(uint32_t* r, uint32_t addr) {
    asm volatile("ldmatrix.sync.aligned.m8n8.x4.shared.b16 {%0,%1,%2,%3}, [%4];"
                 : "=r"(r[0]), "=r"(r[1]), "=r"(r[2]), "=r"(r[3]) : "r"(addr));
}
__device__ __forceinline__ void mma16816(float* c, const uint32_t* a, const uint32_t* b) {
    asm volatile(
        "mma.sync.aligned.m16n8k16.row.col.f32.bf16.bf16.f32 "
        "{%0,%1,%2,%3}, {%4,%5,%6,%7}, {%8,%9}, {%0,%1,%2,%3};"
        : "+f"(c[0]), "+f"(c[1]), "+f"(c[2]), "+f"(c[3])
        : "r"(a[0]), "r"(a[1]), "r"(a[2]), "r"(a[3]), "r"(b[0]), "r"(b[1]));
}
__device__ __forceinline__ uint32_t pack2(__nv_bfloat16 a, __nv_bfloat16 b) {
    return (uint32_t)__bfloat16_as_ushort(a) | ((uint32_t)__bfloat16_as_ushort(b) << 16);
}

// ---------------- dispatch ------------------------------------------------------
__global__ void k_sniff(const int* __restrict__ w32) {
    __shared__ int acc;
    if (threadIdx.x == 0) acc = 0;
    __syncthreads();
    int o = 0;
    for (int i = threadIdx.x; i < TKN / 2; i += blockDim.x) o |= w32[2 * i + 1];
    atomicOr(&acc, o);
    __syncthreads();
    if (threadIdx.x == 0) {
        g_is64 = (acc == 0) ? 1 : 0;
        for (int e = 0; e < E_; e++) g_cnt[e] = 0;
    }
}
__device__ __forceinline__ int ld_e(const int* w32, int s) {
    return (g_is64 ? w32[2 * s] : w32[s]) & (E_ - 1);
}
__global__ void k_count(const int* __restrict__ idx32) {
    int s = blockIdx.x * blockDim.x + threadIdx.x;
    if (s < TKN) atomicAdd(&g_cnt[ld_e(idx32, s)], 1);
}
__global__ void k_scan() {
    int acc = 0;
    for (int e = 0; e < E_; e++) { g_off[e] = acc; g_cur[e] = acc; acc += g_cnt[e]; }
    g_off[E_] = acc;
}
__global__ void k_scatter(const int* __restrict__ idx32) {
    int s = blockIdx.x * blockDim.x + threadIdx.x;
    if (s < TKN) {
        int e = ld_e(idx32, s);
        int p = atomicAdd(&g_cur[e], 1);
        g_tok[p] = s / KSEL;
        g_pos[s] = (p - g_off[e] < CAP) ? p : -1;
    }
}

// ---------------- conversions ---------------------------------------------------
__global__ void k_cvt_x(const float4* __restrict__ x) {
    int i = blockIdx.x * blockDim.x + threadIdx.x;
    float4 v = x[i];
    __nv_bfloat16 h0 = __float2bfloat16(v.x), h1 = __float2bfloat16(v.y),
                  h2 = __float2bfloat16(v.z), h3 = __float2bfloat16(v.w);
    __nv_bfloat16 l0 = __float2bfloat16(v.x - __bfloat162float(h0));
    __nv_bfloat16 l1 = __float2bfloat16(v.y - __bfloat162float(h1));
    __nv_bfloat16 l2 = __float2bfloat16(v.z - __bfloat162float(h2));
    __nv_bfloat16 l3 = __float2bfloat16(v.w - __bfloat162float(h3));
    ((uint2*)g_xhi)[i] = make_uint2(pack2(h0, h1), pack2(h2, h3));
    ((uint2*)g_xlo)[i] = make_uint2(pack2(l0, l1), pack2(l2, l3));
}

__global__ void k_cvt_w(const float* __restrict__ wg, const float* __restrict__ wu,
                        const float* __restrict__ wd) {
    int z = blockIdx.z, m = z >> 4, e = z & 15;
    int R = (m == 2) ? FF : DIM;
    int C = (m == 2) ? DIM : FF;
    const float* src = (m == 0 ? wg : m == 1 ? wu : wd) + (size_t)e * DIM * FF;
    __nv_bfloat16* dh = (m == 0 ? g_wgThi : m == 1 ? g_wuThi : g_wdThi) + (size_t)e * DIM * FF;
    __nv_bfloat16* dl = (m == 0 ? g_wgTlo : m == 1 ? g_wuTlo : g_wdTlo) + (size_t)e * DIM * FF;
    int c0 = blockIdx.x * 32, r0 = blockIdx.y * 32;
    if (c0 >= C || r0 >= R) return;
    __shared__ float t[32][33];
    int tx = threadIdx.x, ty = threadIdx.y;
#pragma unroll
    for (int i = 0; i < 4; i++)
        t[ty + i * 8][tx] = src[(size_t)(r0 + ty + i * 8) * C + c0 + tx];
    __syncthreads();
#pragma unroll
    for (int i = 0; i < 4; i++) {
        float v = t[tx][ty + i * 8];
        __nv_bfloat16 h = __float2bfloat16(v);
        __nv_bfloat16 l = __float2bfloat16(v - __bfloat162float(h));
        size_t o = (size_t)(c0 + ty + i * 8) * R + r0 + tx;
        dh[o] = h;
        dl[o] = l;
    }
}

// ---------------- GEMM1: h = silu(X Wg)*(X Wu), bf16x3 HMMA ---------------------
// stage (16KB): Ahi[128x16] 4096 | Alo 4096 | Bgh[64x16] 2048 | Bgl 2048 | Buh | Bul
__global__ __launch_bounds__(256, 1) void k_gemm1() {
    __shared__ int stok[128];
    __shared__ __align__(16) char sbuf[2][16384];

    int e = blockIdx.z;
    int base = g_off[e], ne = g_off[e + 1] - base;
    int m0 = blockIdx.y * 128;
    if (m0 >= ne) return;
    int n0 = blockIdx.x * 64;

    int tid = threadIdx.x, lane = tid & 31, wid = tid >> 5;
    int wm = wid >> 1, wn = wid & 1;

    if (tid < 128) {
        int r = m0 + tid;
        stok[tid] = g_tok[base + (r < ne ? r : ne - 1)];
    }
    __syncthreads();

    size_t wb = ((size_t)e * FF + n0) * DIM;
    const __nv_bfloat16* wgh = g_wgThi + wb;
    const __nv_bfloat16* wgl = g_wgTlo + wb;
    const __nv_bfloat16* wuh = g_wuThi + wb;
    const __nv_bfloat16* wul = g_wuTlo + wb;

    int ar = tid >> 1, aci = tid & 1;
    int bh_ = tid >> 7, br = (tid >> 1) & 63, bci = tid & 1;

    auto ldstage = [&](int s, int k0) {
        uint32_t sb = smem_u32(sbuf[s]);
        size_t ga = (size_t)stok[ar] * DIM + k0 + aci * 8;
        uint32_t sa = ar * 32 + aci * 16;
        cpa16(sb + sa, g_xhi + ga);
        cpa16(sb + 4096 + sa, g_xlo + ga);
        size_t gb = (size_t)br * DIM + k0 + bci * 8;
        uint32_t sB = br * 32 + bci * 16;
        cpa16(sb + 8192 + bh_ * 2048 + sB, (bh_ ? wgl : wgh) + gb);
        cpa16(sb + 12288 + bh_ * 2048 + sB, (bh_ ? wul : wuh) + gb);
    };

    float acc_g[2][4][4] = {};
    float acc_u[2][4][4] = {};

    ldstage(0, 0);
    CPA_COMMIT();

    const int NIT = DIM / 16;
    uint32_t aoff = (wm * 32 + (lane & 15)) * 32 + (lane >> 4) * 16;
    uint32_t bbase = (wn * 32 + ((lane >> 4) << 3) + (lane & 7)) * 32 + ((lane >> 3) & 1) * 16;

    for (int it = 0; it < NIT; it++) {
        int s = it & 1;
        if (it + 1 < NIT) { ldstage(s ^ 1, (it + 1) * 16); CPA_COMMIT(); CPA_WAIT1(); }
        else CPA_WAIT0();
        __syncthreads();

        uint32_t sb = smem_u32(sbuf[s]);
        uint32_t ah[2][4], al[2][4];
        ldm4(ah[0], sb + aoff);
        ldm4(ah[1], sb + aoff + 512);
        ldm4(al[0], sb + 4096 + aoff);
        ldm4(al[1], sb + 4096 + aoff + 512);

#pragma unroll
        for (int half = 0; half < 2; half++) {
            uint32_t bo = bbase + half * 512;
            uint32_t bgh[4], bgl[4], buh[4], bul[4];
            ldm4(bgh, sb + 8192 + bo);
            ldm4(bgl, sb + 10240 + bo);
            ldm4(buh, sb + 12288 + bo);
            ldm4(bul, sb + 14336 + bo);
#pragma unroll
            for (int mt = 0; mt < 2; mt++)
#pragma unroll
                for (int q = 0; q < 2; q++) {
                    int nt = half * 2 + q;
                    mma16816(acc_g[mt][nt], ah[mt], &bgh[q * 2]);
                    mma16816(acc_g[mt][nt], ah[mt], &bgl[q * 2]);
                    mma16816(acc_g[mt][nt], al[mt], &bgh[q * 2]);
                    mma16816(acc_u[mt][nt], ah[mt], &buh[q * 2]);
                    mma16816(acc_u[mt][nt], ah[mt], &bul[q * 2]);
                    mma16816(acc_u[mt][nt], al[mt], &buh[q * 2]);
                }
        }
        __syncthreads();
    }

#pragma unroll
    for (int mt = 0; mt < 2; mt++)
#pragma unroll
        for (int nt = 0; nt < 4; nt++) {
            int col = n0 + wn * 32 + nt * 8 + 2 * (lane & 3);
#pragma unroll
            for (int rp = 0; rp < 2; rp++) {
                int tr = wm * 32 + mt * 16 + (lane >> 2) + rp * 8;
                if (m0 + tr < ne) {
                    float gg0 = acc_g[mt][nt][rp * 2], gg1 = acc_g[mt][nt][rp * 2 + 1];
                    float uu0 = acc_u[mt][nt][rp * 2], uu1 = acc_u[mt][nt][rp * 2 + 1];
                    float h0 = gg0 / (1.f + __expf(-gg0)) * uu0;
                    float h1 = gg1 / (1.f + __expf(-gg1)) * uu1;
                    __nv_bfloat16 h0h = __float2bfloat16(h0);
                    __nv_bfloat16 h1h = __float2bfloat16(h1);
                    __nv_bfloat16 h0l = __float2bfloat16(h0 - __bfloat162float(h0h));
                    __nv_bfloat16 h1l = __float2bfloat16(h1 - __bfloat162float(h1h));
                    size_t o = (size_t)(base + m0 + tr) * FF + col;
                    *(uint32_t*)(g_hhi + o) = pack2(h0h, h1h);
                    *(uint32_t*)(g_hlo + o) = pack2(h0l, h1l);
                }
            }
        }
}

// ---------------- GEMM2: y = h Wd, bf16x3 HMMA ----------------------------------
// stage (12KB): Ahi 4096 | Alo 4096 | Bh 2048 | Bl 2048
__global__ __launch_bounds__(256, 1) void k_gemm2() {
    __shared__ __align__(16) char sbuf[2][12288];

    int e = blockIdx.z;
    int base = g_off[e], ne = g_off[e + 1] - base;
    int m0 = blockIdx.y * 128;
    if (m0 >= ne) return;
    int n0 = blockIdx.x * 64;

    int tid = threadIdx.x, lane = tid & 31, wid = tid >> 5;
    int wm = wid >> 1, wn = wid & 1;

    size_t wb = ((size_t)e * DIM + n0) * FF;
    const __nv_bfloat16* wdh = g_wdThi + wb;
    const __nv_bfloat16* wdl = g_wdTlo + wb;

    int ar = tid >> 1, aci = tid & 1;
    int arr = m0 + ar; if (arr >= ne) arr = ne - 1;
    size_t arow = (size_t)(base + arr) * FF;
    int bh_ = tid >> 7, br = (tid >> 1) & 63, bci = tid & 1;

    auto ldstage = [&](int s, int k0) {
        uint32_t sb = smem_u32(sbuf[s]);
        uint32_t sa = ar * 32 + aci * 16;
        cpa16(sb + sa, g_hhi + arow + k0 + aci * 8);
        cpa16(sb + 4096 + sa, g_hlo + arow + k0 + aci * 8);
        size_t gb = (size_t)br * FF + k0 + bci * 8;
        uint32_t sB = br * 32 + bci * 16;
        cpa16(sb + 8192 + bh_ * 2048 + sB, (bh_ ? wdl : wdh) + gb);
    };

    float acc[2][4][4] = {};

    ldstage(0, 0);
    CPA_COMMIT();

    const int NIT = FF / 16;
    uint32_t aoff = (wm * 32 + (lane & 15)) * 32 + (lane >> 4) * 16;
    uint32_t bbase = (wn * 32 + ((lane >> 4) << 3) + (lane & 7)) * 32 + ((lane >> 3) & 1) * 16;

    for (int it = 0; it < NIT; it++) {
        int s = it & 1;
        if (it + 1 < NIT) { ldstage(s ^ 1, (it + 1) * 16); CPA_COMMIT(); CPA_WAIT1(); }
        else CPA_WAIT0();
        __syncthreads();

        uint32_t sb = smem_u32(sbuf[s]);
        uint32_t ah[2][4], al[2][4];
        ldm4(ah[0], sb + aoff);
        ldm4(ah[1], sb + aoff + 512);
        ldm4(al[0], sb + 4096 + aoff);
        ldm4(al[1], sb + 4096 + aoff + 512);

#pragma unroll
        for (int half = 0; half < 2; half++) {
            uint32_t bo = bbase + half * 512;
            uint32_t bh4[4], bl4[4];
            ldm4(bh4, sb + 8192 + bo);
            ldm4(bl4, sb + 10240 + bo);
#pragma unroll
            for (int mt = 0; mt < 2; mt++)
#pragma unroll
                for (int q = 0; q < 2; q++) {
                    int nt = half * 2 + q;
                    mma16816(acc[mt][nt], ah[mt], &bh4[q * 2]);
                    mma16816(acc[mt][nt], ah[mt], &bl4[q * 2]);
                    mma16816(acc[mt][nt], al[mt], &bh4[q * 2]);
                }
        }
        __syncthreads();
    }

#pragma unroll
    for (int mt = 0; mt < 2; mt++)
#pragma unroll
        for (int nt = 0; nt < 4; nt++) {
            int col = n0 + wn * 32 + nt * 8 + 2 * (lane & 3);
#pragma unroll
            for (int rp = 0; rp < 2; rp++) {
                int tr = wm * 32 + mt * 16 + (lane >> 2) + rp * 8;
                if (m0 + tr < ne) {
                    float2* yo = (float2*)(g_y + (size_t)(base + m0 + tr) * DIM + col);
                    *yo = make_float2(acc[mt][nt][rp * 2], acc[mt][nt][rp * 2 + 1]);
                }
            }
        }
}

// ---------------- combine -------------------------------------------------------
__global__ void k_combine(const float* __restrict__ w, float4* __restrict__ out) {
    int i = blockIdx.x * blockDim.x + threadIdx.x;
    int t = i >> 8;
    int d4 = i & 255;
    int p0 = g_pos[2 * t], p1 = g_pos[2 * t + 1];
    float w0 = (p0 < 0) ? 0.f : w[2 * t];
    float w1 = (p1 < 0) ? 0.f : w[2 * t + 1];
    int q0 = p0 < 0 ? 0 : p0, q1 = p1 < 0 ? 0 : p1;
    const float4* y4 = (const float4*)g_y;
    float4 a = y4[(size_t)q0 * 256 + d4];
    float4 b = y4[(size_t)q1 * 256 + d4];
    out[i] = make_float4(w0 * a.x + w1 * b.x, w0 * a.y + w1 * b.y,
                         w0 * a.z + w1 * b.z, w0 * a.w + w1 * b.w);
}

// ---------------- launch --------------------------------------------------------
extern "C" void kernel_launch(void* const* d_in, const int* in_sizes, int n_in,
                              void* d_out, int out_size) {
    const float* x     = (const float*)d_in[0];
    const int*   idx32 = (const int*)d_in[1];
    const float* w     = (const float*)d_in[2];
    const float* wg    = (const float*)d_in[3];
    const float* wu    = (const float*)d_in[4];
    const float* wd    = (const float*)d_in[5];
    float*       out   = (float*)d_out;

    k_sniff<<<1, 256>>>(idx32);
    k_count<<<(TKN + 255) / 256, 256>>>(idx32);
    k_scan<<<1, 1>>>();
    k_scatter<<<(TKN + 255) / 256, 256>>>(idx32);

    k_cvt_x<<<(TOK * DIM / 4) / 256, 256>>>((const float4*)x);
    k_cvt_w<<<dim3(32, 32, 48), dim3(32, 8)>>>(wg, wu, wd);

    k_gemm1<<<dim3(FF / 64, CAP / 128, E_), 256>>>();
    k_gemm2<<<dim3(DIM / 64, CAP / 128, E_), 256>>>();

    k_combine<<<(TOK * DIM / 4) / 256, 256>>>(w, (float4*)out);
}

// round 7
// speedup vs baseline: 1.5701x; 1.5464x over previous
#include <cuda_runtime.h>
#include <cuda_bf16.h>
#include <cstdint>

#define E_   16
#define KSEL 2
#define DIM  1024
#define FF   512
#define TOK  4096
#define TKN  (TOK * KSEL)
#define CAP  2048          // per-expert capacity (matches reference C)

// ---------------- device scratch ----------------------------------------------
__device__ int g_off[E_ + 1];
__device__ int g_tok[TKN];
__device__ int g_pos[TKN];          // flat slot -> compacted pos, -1 if dropped
__device__ __align__(16) __nv_bfloat16 g_xhi[(size_t)TOK * DIM];
__device__ __align__(16) __nv_bfloat16 g_xlo[(size_t)TOK * DIM];
__device__ __align__(16) __nv_bfloat16 g_wgThi[(size_t)E_ * FF * DIM];
__device__ __align__(16) __nv_bfloat16 g_wgTlo[(size_t)E_ * FF * DIM];
__device__ __align__(16) __nv_bfloat16 g_wuThi[(size_t)E_ * FF * DIM];
__device__ __align__(16) __nv_bfloat16 g_wuTlo[(size_t)E_ * FF * DIM];
__device__ __align__(16) __nv_bfloat16 g_wdThi[(size_t)E_ * DIM * FF];
__device__ __align__(16) __nv_bfloat16 g_wdTlo[(size_t)E_ * DIM * FF];
__device__ __align__(16) __nv_bfloat16 g_hhi[(size_t)TKN * FF];
__device__ __align__(16) __nv_bfloat16 g_hlo[(size_t)TKN * FF];
__device__ __align__(16) float g_y[(size_t)TKN * DIM];

// ---------------- helpers -------------------------------------------------------
__device__ __forceinline__ uint32_t smem_u32(const void* p) {
    uint32_t a;
    asm("{ .reg .u64 t; cvta.to.shared.u64 t, %1; cvt.u32.u64 %0, t; }" : "=r"(a) : "l"(p));
    return a;
}
__device__ __forceinline__ void cpa16(uint32_t sm, const void* g) {
    asm volatile("cp.async.ca.shared.global [%0], [%1], 16;" :: "r"(sm), "l"(g));
}
#define CPA_COMMIT() asm volatile("cp.async.commit_group;" ::: "memory")
#define CPA_WAIT0()  asm volatile("cp.async.wait_group 0;" ::: "memory")
#define CPA_WAIT1()  asm volatile("cp.async.wait_group 1;" ::: "memory")

__device__ __forceinline__ void ldm4(uint32_t* r, uint32_t addr) {
    asm volatile("ldmatrix.sync.aligned.m8n8.x4.shared.b16 {%0,%1,%2,%3}, [%4];"
                 : "=r"(r[0]), "=r"(r[1]), "=r"(r[2]), "=r"(r[3]) : "r"(addr));
}
__device__ __forceinline__ void mma16816(float* c, const uint32_t* a, const uint32_t* b) {
    asm volatile(
        "mma.sync.aligned.m16n8k16.row.col.f32.bf16.bf16.f32 "
        "{%0,%1,%2,%3}, {%4,%5,%6,%7}, {%8,%9}, {%0,%1,%2,%3};"
        : "+f"(c[0]), "+f"(c[1]), "+f"(c[2]), "+f"(c[3])
        : "r"(a[0]), "r"(a[1]), "r"(a[2]), "r"(a[3]), "r"(b[0]), "r"(b[1]));
}
__device__ __forceinline__ uint32_t pack2(__nv_bfloat16 a, __nv_bfloat16 b) {
    return (uint32_t)__bfloat16_as_ushort(a) | ((uint32_t)__bfloat16_as_ushort(b) << 16);
}

// ---------------- fused dispatch (single CTA) -----------------------------------
__global__ void k_dispatch(const int* __restrict__ w32) {
    __shared__ int s_acc;
    __shared__ int s_cnt[E_];
    __shared__ int s_off[E_ + 1];
    __shared__ int s_cur[E_];
    int tid = threadIdx.x;

    if (tid == 0) s_acc = 0;
    if (tid < E_) s_cnt[tid] = 0;
    __syncthreads();

    // dtype sniff: int64-LE => all odd 32-bit words are zero high-halves
    int o = 0;
    for (int i = tid; i < TKN / 2; i += blockDim.x) o |= w32[2 * i + 1];
    atomicOr(&s_acc, o);
    __syncthreads();
    int is64 = (s_acc == 0) ? 1 : 0;

    // count
    for (int s = tid; s < TKN; s += blockDim.x) {
        int e = (is64 ? w32[2 * s] : w32[s]) & (E_ - 1);
        atomicAdd(&s_cnt[e], 1);
    }
    __syncthreads();

    // scan
    if (tid == 0) {
        int acc = 0;
        for (int e = 0; e < E_; e++) {
            s_off[e] = acc;
            s_cur[e] = acc;
            g_off[e] = acc;
            acc += s_cnt[e];
        }
        s_off[E_] = acc;
        g_off[E_] = acc;
    }
    __syncthreads();

    // scatter
    for (int s = tid; s < TKN; s += blockDim.x) {
        int e = (is64 ? w32[2 * s] : w32[s]) & (E_ - 1);
        int p = atomicAdd(&s_cur[e], 1);
        g_tok[p] = s / KSEL;
        g_pos[s] = (p - s_off[e] < CAP) ? p : -1;
    }
}

// ---------------- conversions ---------------------------------------------------
__global__ void k_cvt_x(const float4* __restrict__ x) {
    int i = blockIdx.x * blockDim.x + threadIdx.x;
    float4 v = x[i];
    __nv_bfloat16 h0 = __float2bfloat16(v.x), h1 = __float2bfloat16(v.y),
                  h2 = __float2bfloat16(v.z), h3 = __float2bfloat16(v.w);
    __nv_bfloat16 l0 = __float2bfloat16(v.x - __bfloat162float(h0));
    __nv_bfloat16 l1 = __float2bfloat16(v.y - __bfloat162float(h1));
    __nv_bfloat16 l2 = __float2bfloat16(v.z - __bfloat162float(h2));
    __nv_bfloat16 l3 = __float2bfloat16(v.w - __bfloat162float(h3));
    ((uint2*)g_xhi)[i] = make_uint2(pack2(h0, h1), pack2(h2, h3));
    ((uint2*)g_xlo)[i] = make_uint2(pack2(l0, l1), pack2(l2, l3));
}

__global__ void k_cvt_w(const float* __restrict__ wg, const float* __restrict__ wu,
                        const float* __restrict__ wd) {
    int z = blockIdx.z, m = z >> 4, e = z & 15;
    int R = (m == 2) ? FF : DIM;
    int C = (m == 2) ? DIM : FF;
    const float* src = (m == 0 ? wg : m == 1 ? wu : wd) + (size_t)e * DIM * FF;
    __nv_bfloat16* dh = (m == 0 ? g_wgThi : m == 1 ? g_wuThi : g_wdThi) + (size_t)e * DIM * FF;
    __nv_bfloat16* dl = (m == 0 ? g_wgTlo : m == 1 ? g_wuTlo : g_wdTlo) + (size_t)e * DIM * FF;
    int c0 = blockIdx.x * 32, r0 = blockIdx.y * 32;
    if (c0 >= C || r0 >= R) return;
    __shared__ float t[32][33];
    int tx = threadIdx.x, ty = threadIdx.y;
#pragma unroll
    for (int i = 0; i < 4; i++)
        t[ty + i * 8][tx] = src[(size_t)(r0 + ty + i * 8) * C + c0 + tx];
    __syncthreads();
#pragma unroll
    for (int i = 0; i < 4; i++) {
        float v = t[tx][ty + i * 8];
        __nv_bfloat16 h = __float2bfloat16(v);
        __nv_bfloat16 l = __float2bfloat16(v - __bfloat162float(h));
        size_t o = (size_t)(c0 + ty + i * 8) * R + r0 + tx;
        dh[o] = h;
        dl[o] = l;
    }
}

// ---------------- GEMM1: h = silu(X Wg)*(X Wu), bf16x3 HMMA ---------------------
__global__ __launch_bounds__(256, 1) void k_gemm1() {
    __shared__ int stok[128];
    __shared__ __align__(16) char sbuf[2][16384];

    int e = blockIdx.z;
    int base = g_off[e], ne = g_off[e + 1] - base;
    int m0 = blockIdx.y * 128;
    if (m0 >= ne) return;
    int n0 = blockIdx.x * 64;

    int tid = threadIdx.x, lane = tid & 31, wid = tid >> 5;
    int wm = wid >> 1, wn = wid & 1;

    if (tid < 128) {
        int r = m0 + tid;
        stok[tid] = g_tok[base + (r < ne ? r : ne - 1)];
    }
    __syncthreads();

    size_t wb = ((size_t)e * FF + n0) * DIM;
    const __nv_bfloat16* wgh = g_wgThi + wb;
    const __nv_bfloat16* wgl = g_wgTlo + wb;
    const __nv_bfloat16* wuh = g_wuThi + wb;
    const __nv_bfloat16* wul = g_wuTlo + wb;

    int ar = tid >> 1, aci = tid & 1;
    int bh_ = tid >> 7, br = (tid >> 1) & 63, bci = tid & 1;

    auto ldstage = [&](int s, int k0) {
        uint32_t sb = smem_u32(sbuf[s]);
        size_t ga = (size_t)stok[ar] * DIM + k0 + aci * 8;
        uint32_t sa = ar * 32 + aci * 16;
        cpa16(sb + sa, g_xhi + ga);
        cpa16(sb + 4096 + sa, g_xlo + ga);
        size_t gb = (size_t)br * DIM + k0 + bci * 8;
        uint32_t sB = br * 32 + bci * 16;
        cpa16(sb + 8192 + bh_ * 2048 + sB, (bh_ ? wgl : wgh) + gb);
        cpa16(sb + 12288 + bh_ * 2048 + sB, (bh_ ? wul : wuh) + gb);
    };

    float acc_g[2][4][4] = {};
    float acc_u[2][4][4] = {};

    ldstage(0, 0);
    CPA_COMMIT();

    const int NIT = DIM / 16;
    uint32_t aoff = (wm * 32 + (lane & 15)) * 32 + (lane >> 4) * 16;
    uint32_t bbase = (wn * 32 + ((lane >> 4) << 3) + (lane & 7)) * 32 + ((lane >> 3) & 1) * 16;

    for (int it = 0; it < NIT; it++) {
        int s = it & 1;
        if (it + 1 < NIT) { ldstage(s ^ 1, (it + 1) * 16); CPA_COMMIT(); CPA_WAIT1(); }
        else CPA_WAIT0();
        __syncthreads();

        uint32_t sb = smem_u32(sbuf[s]);
        uint32_t ah[2][4], al[2][4];
        ldm4(ah[0], sb + aoff);
        ldm4(ah[1], sb + aoff + 512);
        ldm4(al[0], sb + 4096 + aoff);
        ldm4(al[1], sb + 4096 + aoff + 512);

#pragma unroll
        for (int half = 0; half < 2; half++) {
            uint32_t bo = bbase + half * 512;
            uint32_t bgh[4], bgl[4], buh[4], bul[4];
            ldm4(bgh, sb + 8192 + bo);
            ldm4(bgl, sb + 10240 + bo);
            ldm4(buh, sb + 12288 + bo);
            ldm4(bul, sb + 14336 + bo);
#pragma unroll
            for (int mt = 0; mt < 2; mt++)
#pragma unroll
                for (int q = 0; q < 2; q++) {
                    int nt = half * 2 + q;
                    mma16816(acc_g[mt][nt], ah[mt], &bgh[q * 2]);
                    mma16816(acc_g[mt][nt], ah[mt], &bgl[q * 2]);
                    mma16816(acc_g[mt][nt], al[mt], &bgh[q * 2]);
                    mma16816(acc_u[mt][nt], ah[mt], &buh[q * 2]);
                    mma16816(acc_u[mt][nt], ah[mt], &bul[q * 2]);
                    mma16816(acc_u[mt][nt], al[mt], &buh[q * 2]);
                }
        }
        __syncthreads();
    }

#pragma unroll
    for (int mt = 0; mt < 2; mt++)
#pragma unroll
        for (int nt = 0; nt < 4; nt++) {
            int col = n0 + wn * 32 + nt * 8 + 2 * (lane & 3);
#pragma unroll
            for (int rp = 0; rp < 2; rp++) {
                int tr = wm * 32 + mt * 16 + (lane >> 2) + rp * 8;
                if (m0 + tr < ne) {
                    float gg0 = acc_g[mt][nt][rp * 2], gg1 = acc_g[mt][nt][rp * 2 + 1];
                    float uu0 = acc_u[mt][nt][rp * 2], uu1 = acc_u[mt][nt][rp * 2 + 1];
                    float h0 = gg0 / (1.f + __expf(-gg0)) * uu0;
                    float h1 = gg1 / (1.f + __expf(-gg1)) * uu1;
                    __nv_bfloat16 h0h = __float2bfloat16(h0);
                    __nv_bfloat16 h1h = __float2bfloat16(h1);
                    __nv_bfloat16 h0l = __float2bfloat16(h0 - __bfloat162float(h0h));
                    __nv_bfloat16 h1l = __float2bfloat16(h1 - __bfloat162float(h1h));
                    size_t o = (size_t)(base + m0 + tr) * FF + col;
                    *(uint32_t*)(g_hhi + o) = pack2(h0h, h1h);
                    *(uint32_t*)(g_hlo + o) = pack2(h0l, h1l);
                }
            }
        }
}

// ---------------- GEMM2: y = h Wd, bf16x3 HMMA ----------------------------------
__global__ __launch_bounds__(256, 1) void k_gemm2() {
    __shared__ __align__(16) char sbuf[2][12288];

    int e = blockIdx.z;
    int base = g_off[e], ne = g_off[e + 1] - base;
    int m0 = blockIdx.y * 128;
    if (m0 >= ne) return;
    int n0 = blockIdx.x * 64;

    int tid = threadIdx.x, lane = tid & 31, wid = tid >> 5;
    int wm = wid >> 1, wn = wid & 1;

    size_t wb = ((size_t)e * DIM + n0) * FF;
    const __nv_bfloat16* wdh = g_wdThi + wb;
    const __nv_bfloat16* wdl = g_wdTlo + wb;

    int ar = tid >> 1, aci = tid & 1;
    int arr = m0 + ar; if (arr >= ne) arr = ne - 1;
    size_t arow = (size_t)(base + arr) * FF;
    int bh_ = tid >> 7, br = (tid >> 1) & 63, bci = tid & 1;

    auto ldstage = [&](int s, int k0) {
        uint32_t sb = smem_u32(sbuf[s]);
        uint32_t sa = ar * 32 + aci * 16;
        cpa16(sb + sa, g_hhi + arow + k0 + aci * 8);
        cpa16(sb + 4096 + sa, g_hlo + arow + k0 + aci * 8);
        size_t gb = (size_t)br * FF + k0 + bci * 8;
        uint32_t sB = br * 32 + bci * 16;
        cpa16(sb + 8192 + bh_ * 2048 + sB, (bh_ ? wdl : wdh) + gb);
    };

    float acc[2][4][4] = {};

    ldstage(0, 0);
    CPA_COMMIT();

    const int NIT = FF / 16;
    uint32_t aoff = (wm * 32 + (lane & 15)) * 32 + (lane >> 4) * 16;
    uint32_t bbase = (wn * 32 + ((lane >> 4) << 3) + (lane & 7)) * 32 + ((lane >> 3) & 1) * 16;

    for (int it = 0; it < NIT; it++) {
        int s = it & 1;
        if (it + 1 < NIT) { ldstage(s ^ 1, (it + 1) * 16); CPA_COMMIT(); CPA_WAIT1(); }
        else CPA_WAIT0();
        __syncthreads();

        uint32_t sb = smem_u32(sbuf[s]);
        uint32_t ah[2][4], al[2][4];
        ldm4(ah[0], sb + aoff);
        ldm4(ah[1], sb + aoff + 512);
        ldm4(al[0], sb + 4096 + aoff);
        ldm4(al[1], sb + 4096 + aoff + 512);

#pragma unroll
        for (int half = 0; half < 2; half++) {
            uint32_t bo = bbase + half * 512;
            uint32_t bh4[4], bl4[4];
            ldm4(bh4, sb + 8192 + bo);
            ldm4(bl4, sb + 10240 + bo);
#pragma unroll
            for (int mt = 0; mt < 2; mt++)
#pragma unroll
                for (int q = 0; q < 2; q++) {
                    int nt = half * 2 + q;
                    mma16816(acc[mt][nt], ah[mt], &bh4[q * 2]);
                    mma16816(acc[mt][nt], ah[mt], &bl4[q * 2]);
                    mma16816(acc[mt][nt], al[mt], &bh4[q * 2]);
                }
        }
        __syncthreads();
    }

#pragma unroll
    for (int mt = 0; mt < 2; mt++)
#pragma unroll
        for (int nt = 0; nt < 4; nt++) {
            int col = n0 + wn * 32 + nt * 8 + 2 * (lane & 3);
#pragma unroll
            for (int rp = 0; rp < 2; rp++) {
                int tr = wm * 32 + mt * 16 + (lane >> 2) + rp * 8;
                if (m0 + tr < ne) {
                    float2* yo = (float2*)(g_y + (size_t)(base + m0 + tr) * DIM + col);
                    *yo = make_float2(acc[mt][nt][rp * 2], acc[mt][nt][rp * 2 + 1]);
                }
            }
        }
}

// ---------------- combine -------------------------------------------------------
__global__ void k_combine(const float* __restrict__ w, float4* __restrict__ out) {
    int i = blockIdx.x * blockDim.x + threadIdx.x;
    int t = i >> 8;
    int d4 = i & 255;
    int p0 = g_pos[2 * t], p1 = g_pos[2 * t + 1];
    float w0 = (p0 < 0) ? 0.f : w[2 * t];
    float w1 = (p1 < 0) ? 0.f : w[2 * t + 1];
    int q0 = p0 < 0 ? 0 : p0, q1 = p1 < 0 ? 0 : p1;
    const float4* y4 = (const float4*)g_y;
    float4 a = y4[(size_t)q0 * 256 + d4];
    float4 b = y4[(size_t)q1 * 256 + d4];
    out[i] = make_float4(w0 * a.x + w1 * b.x, w0 * a.y + w1 * b.y,
                         w0 * a.z + w1 * b.z, w0 * a.w + w1 * b.w);
}

// ---------------- launch --------------------------------------------------------
extern "C" void kernel_launch(void* const* d_in, const int* in_sizes, int n_in,
                              void* d_out, int out_size) {
    const float* x     = (const float*)d_in[0];
    const int*   idx32 = (const int*)d_in[1];
    const float* w     = (const float*)d_in[2];
    const float* wg    = (const float*)d_in[3];
    const float* wu    = (const float*)d_in[4];
    const float* wd    = (const float*)d_in[5];
    float*       out   = (float*)d_out;

    // launch index 3 (k_gemm1) is the one ncu captures — keep it there.
    k_dispatch<<<1, 256>>>(idx32);                                  // 0
    k_cvt_x<<<(TOK * DIM / 4) / 256, 256>>>((const float4*)x);      // 1
    k_cvt_w<<<dim3(32, 32, 48), dim3(32, 8)>>>(wg, wu, wd);         // 2
    k_gemm1<<<dim3(FF / 64, CAP / 128, E_), 256>>>();               // 3  <- profiled
    k_gemm2<<<dim3(DIM / 64, CAP / 128, E_), 256>>>();              // 4
    k_combine<<<(TOK * DIM / 4) / 256, 256>>>(w, (float4*)out);     // 5
}

// round 8
// speedup vs baseline: 1.7259x; 1.0992x over previous
#include <cuda_runtime.h>
#include <cuda_bf16.h>
#include <cstdint>

#define E_   16
#define KSEL 2
#define DIM  1024
#define FF   512
#define TOK  4096
#define TKN  (TOK * KSEL)
#define CAP  2048          // per-expert capacity (matches reference C)

// ---------------- device scratch ----------------------------------------------
__device__ int g_off[E_ + 1];
__device__ int g_tok[TKN];
__device__ int g_pos[TKN];          // flat slot -> compacted pos, -1 if dropped
__device__ __align__(16) __nv_bfloat16 g_xhi[(size_t)TOK * DIM];
__device__ __align__(16) __nv_bfloat16 g_xlo[(size_t)TOK * DIM];
__device__ __align__(16) __nv_bfloat16 g_wgThi[(size_t)E_ * FF * DIM];
__device__ __align__(16) __nv_bfloat16 g_wgTlo[(size_t)E_ * FF * DIM];
__device__ __align__(16) __nv_bfloat16 g_wuThi[(size_t)E_ * FF * DIM];
__device__ __align__(16) __nv_bfloat16 g_wuTlo[(size_t)E_ * FF * DIM];
__device__ __align__(16) __nv_bfloat16 g_wdThi[(size_t)E_ * DIM * FF];
__device__ __align__(16) __nv_bfloat16 g_wdTlo[(size_t)E_ * DIM * FF];
__device__ __align__(16) __nv_bfloat16 g_hhi[(size_t)TKN * FF];
__device__ __align__(16) __nv_bfloat16 g_hlo[(size_t)TKN * FF];
__device__ __align__(16) float g_y[(size_t)TKN * DIM];

// ---------------- helpers -------------------------------------------------------
__device__ __forceinline__ uint32_t smem_u32(const void* p) {
    uint32_t a;
    asm("{ .reg .u64 t; cvta.to.shared.u64 t, %1; cvt.u32.u64 %0, t; }" : "=r"(a) : "l"(p));
    return a;
}
__device__ __forceinline__ void cpa16(uint32_t sm, const void* g) {
    asm volatile("cp.async.ca.shared.global [%0], [%1], 16;" :: "r"(sm), "l"(g));
}
#define CPA_COMMIT() asm volatile("cp.async.commit_group;" ::: "memory")
#define CPA_WAIT1()  asm volatile("cp.async.wait_group 1;" ::: "memory")

__device__ __forceinline__ void ldm4(uint32_t* r, uint32_t addr) {
    asm volatile("ldmatrix.sync.aligned.m8n8.x4.shared.b16 {%0,%1,%2,%3}, [%4];"
                 : "=r"(r[0]), "=r"(r[1]), "=r"(r[2]), "=r"(r[3]) : "r"(addr));
}
__device__ __forceinline__ void mma16816(float* c, const uint32_t* a, const uint32_t* b) {
    asm volatile(
        "mma.sync.aligned.m16n8k16.row.col.f32.bf16.bf16.f32 "
        "{%0,%1,%2,%3}, {%4,%5,%6,%7}, {%8,%9}, {%0,%1,%2,%3};"
        : "+f"(c[0]), "+f"(c[1]), "+f"(c[2]), "+f"(c[3])
        : "r"(a[0]), "r"(a[1]), "r"(a[2]), "r"(a[3]), "r"(b[0]), "r"(b[1]));
}
__device__ __forceinline__ uint32_t pack2(__nv_bfloat16 a, __nv_bfloat16 b) {
    return (uint32_t)__bfloat16_as_ushort(a) | ((uint32_t)__bfloat16_as_ushort(b) << 16);
}

// ---------------- fused dispatch (single CTA) -----------------------------------
__global__ void k_dispatch(const int* __restrict__ w32) {
    __shared__ int s_acc;
    __shared__ int s_cnt[E_];
    __shared__ int s_off[E_ + 1];
    __shared__ int s_cur[E_];
    int tid = threadIdx.x;

    if (tid == 0) s_acc = 0;
    if (tid < E_) s_cnt[tid] = 0;
    __syncthreads();

    int o = 0;
    for (int i = tid; i < TKN / 2; i += blockDim.x) o |= w32[2 * i + 1];
    atomicOr(&s_acc, o);
    __syncthreads();
    int is64 = (s_acc == 0) ? 1 : 0;

    for (int s = tid; s < TKN; s += blockDim.x) {
        int e = (is64 ? w32[2 * s] : w32[s]) & (E_ - 1);
        atomicAdd(&s_cnt[e], 1);
    }
    __syncthreads();

    if (tid == 0) {
        int acc = 0;
        for (int e = 0; e < E_; e++) {
            s_off[e] = acc;
            s_cur[e] = acc;
            g_off[e] = acc;
            acc += s_cnt[e];
        }
        s_off[E_] = acc;
        g_off[E_] = acc;
    }
    __syncthreads();

    for (int s = tid; s < TKN; s += blockDim.x) {
        int e = (is64 ? w32[2 * s] : w32[s]) & (E_ - 1);
        int p = atomicAdd(&s_cur[e], 1);
        g_tok[p] = s / KSEL;
        g_pos[s] = (p - s_off[e] < CAP) ? p : -1;
    }
}

// ---------------- conversions ---------------------------------------------------
__global__ void k_cvt_x(const float4* __restrict__ x) {
    int i = blockIdx.x * blockDim.x + threadIdx.x;
    float4 v = x[i];
    __nv_bfloat16 h0 = __float2bfloat16(v.x), h1 = __float2bfloat16(v.y),
                  h2 = __float2bfloat16(v.z), h3 = __float2bfloat16(v.w);
    __nv_bfloat16 l0 = __float2bfloat16(v.x - __bfloat162float(h0));
    __nv_bfloat16 l1 = __float2bfloat16(v.y - __bfloat162float(h1));
    __nv_bfloat16 l2 = __float2bfloat16(v.z - __bfloat162float(h2));
    __nv_bfloat16 l3 = __float2bfloat16(v.w - __bfloat162float(h3));
    ((uint2*)g_xhi)[i] = make_uint2(pack2(h0, h1), pack2(h2, h3));
    ((uint2*)g_xlo)[i] = make_uint2(pack2(l0, l1), pack2(l2, l3));
}

__global__ void k_cvt_w(const float* __restrict__ wg, const float* __restrict__ wu,
                        const float* __restrict__ wd) {
    int z = blockIdx.z, m = z >> 4, e = z & 15;
    int R = (m == 2) ? FF : DIM;
    int C = (m == 2) ? DIM : FF;
    const float* src = (m == 0 ? wg : m == 1 ? wu : wd) + (size_t)e * DIM * FF;
    __nv_bfloat16* dh = (m == 0 ? g_wgThi : m == 1 ? g_wuThi : g_wdThi) + (size_t)e * DIM * FF;
    __nv_bfloat16* dl = (m == 0 ? g_wgTlo : m == 1 ? g_wuTlo : g_wdTlo) + (size_t)e * DIM * FF;
    int c0 = blockIdx.x * 32, r0 = blockIdx.y * 32;
    if (c0 >= C || r0 >= R) return;
    __shared__ float t[32][33];
    int tx = threadIdx.x, ty = threadIdx.y;
#pragma unroll
    for (int i = 0; i < 4; i++)
        t[ty + i * 8][tx] = src[(size_t)(r0 + ty + i * 8) * C + c0 + tx];
    __syncthreads();
#pragma unroll
    for (int i = 0; i < 4; i++) {
        float v = t[tx][ty + i * 8];
        __nv_bfloat16 h = __float2bfloat16(v);
        __nv_bfloat16 l = __float2bfloat16(v - __bfloat162float(h));
        size_t o = (size_t)(c0 + ty + i * 8) * R + r0 + tx;
        dh[o] = h;
        dl[o] = l;
    }
}

// ---------------- GEMM1: h = silu(X Wg)*(X Wu), bf16x3 HMMA ---------------------
// 3-stage cp.async pipeline, one __syncthreads per k-iter.
// stage (16KB): Ahi[128x16] 4096 | Alo 4096 | Bgh 2048 | Bgl 2048 | Buh 2048 | Bul 2048
__global__ __launch_bounds__(256, 1) void k_gemm1() {
    __shared__ __align__(16) char sbuf[3][16384];

    int e = blockIdx.z;
    int base = g_off[e], ne = g_off[e + 1] - base;
    int m0 = blockIdx.y * 128;
    if (m0 >= ne) return;
    int n0 = blockIdx.x * 64;

    int tid = threadIdx.x, lane = tid & 31, wid = tid >> 5;
    int wm = wid >> 1, wn = wid & 1;

    size_t wb = ((size_t)e * FF + n0) * DIM;
    const __nv_bfloat16* wgh = g_wgThi + wb;
    const __nv_bfloat16* wgl = g_wgTlo + wb;
    const __nv_bfloat16* wuh = g_wuThi + wb;
    const __nv_bfloat16* wul = g_wuTlo + wb;

    // A-load mapping: row = tid>>1 (fixed per thread) -> token in a register
    int ar = tid >> 1, aci = tid & 1;
    int arow_ = m0 + ar; if (arow_ >= ne) arow_ = ne - 1;
    size_t tokrow = (size_t)g_tok[base + arow_] * DIM;
    int bh_ = tid >> 7, br = (tid >> 1) & 63, bci = tid & 1;

    uint32_t sb_base = smem_u32(sbuf);
    auto ldstage = [&](int s, int it) {
        uint32_t sb = sb_base + s * 16384;
        int k0 = it * 16;
        uint32_t sa = ar * 32 + aci * 16;
        cpa16(sb + sa, g_xhi + tokrow + k0 + aci * 8);
        cpa16(sb + 4096 + sa, g_xlo + tokrow + k0 + aci * 8);
        size_t gb = (size_t)br * DIM + k0 + bci * 8;
        uint32_t sB = br * 32 + bci * 16;
        cpa16(sb + 8192 + bh_ * 2048 + sB, (bh_ ? wgl : wgh) + gb);
        cpa16(sb + 12288 + bh_ * 2048 + sB, (bh_ ? wul : wuh) + gb);
    };

    float acc_g[2][4][4] = {};
    float acc_u[2][4][4] = {};

    ldstage(0, 0); CPA_COMMIT();
    ldstage(1, 1); CPA_COMMIT();

    const int NIT = DIM / 16;
    uint32_t aoff = (wm * 32 + (lane & 15)) * 32 + (lane >> 4) * 16;
    uint32_t bbase = (wn * 32 + ((lane >> 4) << 3) + (lane & 7)) * 32 + ((lane >> 3) & 1) * 16;

    int s = 0;
    for (int it = 0; it < NIT; it++) {
        CPA_WAIT1();            // stage s complete (<=1 group pending)
        __syncthreads();        // all warps see stage s; all done computing s-1 epoch

        if (it + 2 < NIT) ldstage((s + 2 >= 3 ? s - 1 : s + 2), it + 2);
        CPA_COMMIT();

        uint32_t sb = sb_base + s * 16384;
        uint32_t ah[2][4], al[2][4];
        ldm4(ah[0], sb + aoff);
        ldm4(ah[1], sb + aoff + 512);
        ldm4(al[0], sb + 4096 + aoff);
        ldm4(al[1], sb + 4096 + aoff + 512);

#pragma unroll
        for (int half = 0; half < 2; half++) {
            uint32_t bo = bbase + half * 512;
            uint32_t bgh[4], bgl[4], buh[4], bul[4];
            ldm4(bgh, sb + 8192 + bo);
            ldm4(bgl, sb + 10240 + bo);
            ldm4(buh, sb + 12288 + bo);
            ldm4(bul, sb + 14336 + bo);
#pragma unroll
            for (int mt = 0; mt < 2; mt++)
#pragma unroll
                for (int q = 0; q < 2; q++) {
                    int nt = half * 2 + q;
                    mma16816(acc_g[mt][nt], ah[mt], &bgh[q * 2]);
                    mma16816(acc_g[mt][nt], ah[mt], &bgl[q * 2]);
                    mma16816(acc_g[mt][nt], al[mt], &bgh[q * 2]);
                    mma16816(acc_u[mt][nt], ah[mt], &buh[q * 2]);
                    mma16816(acc_u[mt][nt], ah[mt], &bul[q * 2]);
                    mma16816(acc_u[mt][nt], al[mt], &buh[q * 2]);
                }
        }
        s = (s + 1 == 3) ? 0 : s + 1;
    }

#pragma unroll
    for (int mt = 0; mt < 2; mt++)
#pragma unroll
        for (int nt = 0; nt < 4; nt++) {
            int col = n0 + wn * 32 + nt * 8 + 2 * (lane & 3);
#pragma unroll
            for (int rp = 0; rp < 2; rp++) {
                int tr = wm * 32 + mt * 16 + (lane >> 2) + rp * 8;
                if (m0 + tr < ne) {
                    float gg0 = acc_g[mt][nt][rp * 2], gg1 = acc_g[mt][nt][rp * 2 + 1];
                    float uu0 = acc_u[mt][nt][rp * 2], uu1 = acc_u[mt][nt][rp * 2 + 1];
                    float h0 = gg0 / (1.f + __expf(-gg0)) * uu0;
                    float h1 = gg1 / (1.f + __expf(-gg1)) * uu1;
                    __nv_bfloat16 h0h = __float2bfloat16(h0);
                    __nv_bfloat16 h1h = __float2bfloat16(h1);
                    __nv_bfloat16 h0l = __float2bfloat16(h0 - __bfloat162float(h0h));
                    __nv_bfloat16 h1l = __float2bfloat16(h1 - __bfloat162float(h1h));
                    size_t o = (size_t)(base + m0 + tr) * FF + col;
                    *(uint32_t*)(g_hhi + o) = pack2(h0h, h1h);
                    *(uint32_t*)(g_hlo + o) = pack2(h0l, h1l);
                }
            }
        }
}

// ---------------- GEMM2: y = h Wd, bf16x3 HMMA ----------------------------------
// 3-stage pipeline; 2 CTAs/SM via launch_bounds.
// stage (12KB): Ahi 4096 | Alo 4096 | Bh 2048 | Bl 2048
__global__ __launch_bounds__(256, 2) void k_gemm2() {
    __shared__ __align__(16) char sbuf[3][12288];

    int e = blockIdx.z;
    int base = g_off[e], ne = g_off[e + 1] - base;
    int m0 = blockIdx.y * 128;
    if (m0 >= ne) return;
    int n0 = blockIdx.x * 64;

    int tid = threadIdx.x, lane = tid & 31, wid = tid >> 5;
    int wm = wid >> 1, wn = wid & 1;

    size_t wb = ((size_t)e * DIM + n0) * FF;
    const __nv_bfloat16* wdh = g_wdThi + wb;
    const __nv_bfloat16* wdl = g_wdTlo + wb;

    int ar = tid >> 1, aci = tid & 1;
    int arr = m0 + ar; if (arr >= ne) arr = ne - 1;
    size_t arow = (size_t)(base + arr) * FF;
    int bh_ = tid >> 7, br = (tid >> 1) & 63, bci = tid & 1;

    uint32_t sb_base = smem_u32(sbuf);
    auto ldstage = [&](int s, int it) {
        uint32_t sb = sb_base + s * 12288;
        int k0 = it * 16;
        uint32_t sa = ar * 32 + aci * 16;
        cpa16(sb + sa, g_hhi + arow + k0 + aci * 8);
        cpa16(sb + 4096 + sa, g_hlo + arow + k0 + aci * 8);
        size_t gb = (size_t)br * FF + k0 + bci * 8;
        uint32_t sB = br * 32 + bci * 16;
        cpa16(sb + 8192 + bh_ * 2048 + sB, (bh_ ? wdl : wdh) + gb);
    };

    float acc[2][4][4] = {};

    ldstage(0, 0); CPA_COMMIT();
    ldstage(1, 1); CPA_COMMIT();

    const int NIT = FF / 16;
    uint32_t aoff = (wm * 32 + (lane & 15)) * 32 + (lane >> 4) * 16;
    uint32_t bbase = (wn * 32 + ((lane >> 4) << 3) + (lane & 7)) * 32 + ((lane >> 3) & 1) * 16;

    int s = 0;
    for (int it = 0; it < NIT; it++) {
        CPA_WAIT1();
        __syncthreads();

        if (it + 2 < NIT) ldstage((s + 2 >= 3 ? s - 1 : s + 2), it + 2);
        CPA_COMMIT();

        uint32_t sb = sb_base + s * 12288;
        uint32_t ah[2][4], al[2][4];
        ldm4(ah[0], sb + aoff);
        ldm4(ah[1], sb + aoff + 512);
        ldm4(al[0], sb + 4096 + aoff);
        ldm4(al[1], sb + 4096 + aoff + 512);

#pragma unroll
        for (int half = 0; half < 2; half++) {
            uint32_t bo = bbase + half * 512;
            uint32_t bh4[4], bl4[4];
            ldm4(bh4, sb + 8192 + bo);
            ldm4(bl4, sb + 10240 + bo);
#pragma unroll
            for (int mt = 0; mt < 2; mt++)
#pragma unroll
                for (int q = 0; q < 2; q++) {
                    int nt = half * 2 + q;
                    mma16816(acc[mt][nt], ah[mt], &bh4[q * 2]);
                    mma16816(acc[mt][nt], ah[mt], &bl4[q * 2]);
                    mma16816(acc[mt][nt], al[mt], &bh4[q * 2]);
                }
        }
        s = (s + 1 == 3) ? 0 : s + 1;
    }

#pragma unroll
    for (int mt = 0; mt < 2; mt++)
#pragma unroll
        for (int nt = 0; nt < 4; nt++) {
            int col = n0 + wn * 32 + nt * 8 + 2 * (lane & 3);
#pragma unroll
            for (int rp = 0; rp < 2; rp++) {
                int tr = wm * 32 + mt * 16 + (lane >> 2) + rp * 8;
                if (m0 + tr < ne) {
                    float2* yo = (float2*)(g_y + (size_t)(base + m0 + tr) * DIM + col);
                    *yo = make_float2(acc[mt][nt][rp * 2], acc[mt][nt][rp * 2 + 1]);
                }
            }
        }
}

// ---------------- combine -------------------------------------------------------
__global__ void k_combine(const float* __restrict__ w, float4* __restrict__ out) {
    int i = blockIdx.x * blockDim.x + threadIdx.x;
    int t = i >> 8;
    int d4 = i & 255;
    int p0 = g_pos[2 * t], p1 = g_pos[2 * t + 1];
    float w0 = (p0 < 0) ? 0.f : w[2 * t];
    float w1 = (p1 < 0) ? 0.f : w[2 * t + 1];
    int q0 = p0 < 0 ? 0 : p0, q1 = p1 < 0 ? 0 : p1;
    const float4* y4 = (const float4*)g_y;
    float4 a = y4[(size_t)q0 * 256 + d4];
    float4 b = y4[(size_t)q1 * 256 + d4];
    out[i] = make_float4(w0 * a.x + w1 * b.x, w0 * a.y + w1 * b.y,
                         w0 * a.z + w1 * b.z, w0 * a.w + w1 * b.w);
}

// ---------------- launch --------------------------------------------------------
extern "C" void kernel_launch(void* const* d_in, const int* in_sizes, int n_in,
                              void* d_out, int out_size) {
    const float* x     = (const float*)d_in[0];
    const int*   idx32 = (const int*)d_in[1];
    const float* w     = (const float*)d_in[2];
    const float* wg    = (const float*)d_in[3];
    const float* wu    = (const float*)d_in[4];
    const float* wd    = (const float*)d_in[5];
    float*       out   = (float*)d_out;

    // launch index 3 (k_gemm1) is the one ncu captures — keep it there.
    k_dispatch<<<1, 256>>>(idx32);                                  // 0
    k_cvt_x<<<(TOK * DIM / 4) / 256, 256>>>((const float4*)x);      // 1
    k_cvt_w<<<dim3(32, 32, 48), dim3(32, 8)>>>(wg, wu, wd);         // 2
    k_gemm1<<<dim3(FF / 64, CAP / 128, E_), 256>>>();               // 3  <- profiled
    k_gemm2<<<dim3(DIM / 64, CAP / 128, E_), 256>>>();              // 4
    k_combine<<<(TOK * DIM / 4) / 256, 256>>>(w, (float4*)out);     // 5
}

// round 10
// speedup vs baseline: 2.2527x; 1.3053x over previous
#include <cuda_runtime.h>
#include <cuda_bf16.h>
#include <cstdint>

#define E_   16
#define KSEL 2
#define DIM  1024
#define FF   512
#define TOK  4096
#define TKN  (TOK * KSEL)
#define CAP  2048          // per-expert capacity (matches reference C)

// ---------------- device scratch ----------------------------------------------
__device__ int g_off[E_ + 1];
__device__ int g_tok[TKN];
__device__ int g_pos[TKN];          // flat slot -> compacted pos, -1 if dropped
__device__ __align__(16) __nv_bfloat16 g_xhi[(size_t)TOK * DIM];
__device__ __align__(16) __nv_bfloat16 g_xlo[(size_t)TOK * DIM];
__device__ __align__(16) __nv_bfloat16 g_wgThi[(size_t)E_ * FF * DIM];
__device__ __align__(16) __nv_bfloat16 g_wgTlo[(size_t)E_ * FF * DIM];
__device__ __align__(16) __nv_bfloat16 g_wuThi[(size_t)E_ * FF * DIM];
__device__ __align__(16) __nv_bfloat16 g_wuTlo[(size_t)E_ * FF * DIM];
__device__ __align__(16) __nv_bfloat16 g_wdThi[(size_t)E_ * DIM * FF];
__device__ __align__(16) __nv_bfloat16 g_wdTlo[(size_t)E_ * DIM * FF];
__device__ __align__(16) __nv_bfloat16 g_hhi[(size_t)TKN * FF];
__device__ __align__(16) __nv_bfloat16 g_hlo[(size_t)TKN * FF];
__device__ __align__(16) float g_y[(size_t)TKN * DIM];

// ---------------- helpers -------------------------------------------------------
__device__ __forceinline__ uint32_t smem_u32(const void* p) {
    uint32_t a;
    asm("{ .reg .u64 t; cvta.to.shared.u64 t, %1; cvt.u32.u64 %0, t; }" : "=r"(a) : "l"(p));
    return a;
}
__device__ __forceinline__ void cpa16(uint32_t sm, const void* g) {
    asm volatile("cp.async.ca.shared.global [%0], [%1], 16;" :: "r"(sm), "l"(g));
}
#define CPA_COMMIT() asm volatile("cp.async.commit_group;" ::: "memory")
#define CPA_WAIT1()  asm volatile("cp.async.wait_group 1;" ::: "memory")

__device__ __forceinline__ void ldm4(uint32_t* r, uint32_t addr) {
    asm volatile("ldmatrix.sync.aligned.m8n8.x4.shared.b16 {%0,%1,%2,%3}, [%4];"
                 : "=r"(r[0]), "=r"(r[1]), "=r"(r[2]), "=r"(r[3]) : "r"(addr));
}
__device__ __forceinline__ void mma16816(float* c, const uint32_t* a, const uint32_t* b) {
    asm volatile(
        "mma.sync.aligned.m16n8k16.row.col.f32.bf16.bf16.f32 "
        "{%0,%1,%2,%3}, {%4,%5,%6,%7}, {%8,%9}, {%0,%1,%2,%3};"
        : "+f"(c[0]), "+f"(c[1]), "+f"(c[2]), "+f"(c[3])
        : "r"(a[0]), "r"(a[1]), "r"(a[2]), "r"(a[3]), "r"(b[0]), "r"(b[1]));
}
__device__ __forceinline__ uint32_t pack2(__nv_bfloat16 a, __nv_bfloat16 b) {
    return (uint32_t)__bfloat16_as_ushort(a) | ((uint32_t)__bfloat16_as_ushort(b) << 16);
}

// ---------------- fused dispatch (single CTA) -----------------------------------
__global__ void k_dispatch(const int* __restrict__ w32) {
    __shared__ int s_acc;
    __shared__ int s_cnt[E_];
    __shared__ int s_off[E_ + 1];
    __shared__ int s_cur[E_];
    int tid = threadIdx.x;

    if (tid == 0) s_acc = 0;
    if (tid < E_) s_cnt[tid] = 0;
    __syncthreads();

    int o = 0;
    for (int i = tid; i < TKN / 2; i += blockDim.x) o |= w32[2 * i + 1];
    atomicOr(&s_acc, o);
    __syncthreads();
    int is64 = (s_acc == 0) ? 1 : 0;

    for (int s = tid; s < TKN; s += blockDim.x) {
        int e = (is64 ? w32[2 * s] : w32[s]) & (E_ - 1);
        atomicAdd(&s_cnt[e], 1);
    }
    __syncthreads();

    if (tid == 0) {
        int acc = 0;
        for (int e = 0; e < E_; e++) {
            s_off[e] = acc;
            s_cur[e] = acc;
            g_off[e] = acc;
            acc += s_cnt[e];
        }
        s_off[E_] = acc;
        g_off[E_] = acc;
    }
    __syncthreads();

    for (int s = tid; s < TKN; s += blockDim.x) {
        int e = (is64 ? w32[2 * s] : w32[s]) & (E_ - 1);
        int p = atomicAdd(&s_cur[e], 1);
        g_tok[p] = s / KSEL;
        g_pos[s] = (p - s_off[e] < CAP) ? p : -1;
    }
}

// ---------------- conversions ---------------------------------------------------
__global__ void k_cvt_x(const float4* __restrict__ x) {
    int i = blockIdx.x * blockDim.x + threadIdx.x;
    float4 v = x[i];
    __nv_bfloat16 h0 = __float2bfloat16(v.x), h1 = __float2bfloat16(v.y),
                  h2 = __float2bfloat16(v.z), h3 = __float2bfloat16(v.w);
    __nv_bfloat16 l0 = __float2bfloat16(v.x - __bfloat162float(h0));
    __nv_bfloat16 l1 = __float2bfloat16(v.y - __bfloat162float(h1));
    __nv_bfloat16 l2 = __float2bfloat16(v.z - __bfloat162float(h2));
    __nv_bfloat16 l3 = __float2bfloat16(v.w - __bfloat162float(h3));
    ((uint2*)g_xhi)[i] = make_uint2(pack2(h0, h1), pack2(h2, h3));
    ((uint2*)g_xlo)[i] = make_uint2(pack2(l0, l1), pack2(l2, l3));
}

__global__ void k_cvt_w(const float* __restrict__ wg, const float* __restrict__ wu,
                        const float* __restrict__ wd) {
    int z = blockIdx.z, m = z >> 4, e = z & 15;
    int R = (m == 2) ? FF : DIM;
    int C = (m == 2) ? DIM : FF;
    const float* src = (m == 0 ? wg : m == 1 ? wu : wd) + (size_t)e * DIM * FF;
    __nv_bfloat16* dh = (m == 0 ? g_wgThi : m == 1 ? g_wuThi : g_wdThi) + (size_t)e * DIM * FF;
    __nv_bfloat16* dl = (m == 0 ? g_wgTlo : m == 1 ? g_wuTlo : g_wdTlo) + (size_t)e * DIM * FF;
    int c0 = blockIdx.x * 32, r0 = blockIdx.y * 32;
    if (c0 >= C || r0 >= R) return;
    __shared__ float t[32][33];
    int tx = threadIdx.x, ty = threadIdx.y;
#pragma unroll
    for (int i = 0; i < 4; i++)
        t[ty + i * 8][tx] = src[(size_t)(r0 + ty + i * 8) * C + c0 + tx];
    __syncthreads();
#pragma unroll
    for (int i = 0; i < 4; i++) {
        float v = t[tx][ty + i * 8];
        __nv_bfloat16 h = __float2bfloat16(v);
        __nv_bfloat16 l = __float2bfloat16(v - __bfloat162float(h));
        size_t o = (size_t)(c0 + ty + i * 8) * R + r0 + tx;
        dh[o] = h;
        dl[o] = l;
    }
}

// ---------------- GEMM1: h = silu(X Wg)*(X Wu), bf16x3 HMMA ---------------------
// 3-stage cp.async pipeline, one __syncthreads per k-iter, conflict-free swizzle.
// Swizzle: 16B-column bit XORed with row bit2 -> ldmatrix 8 row-ptrs hit 8 banks.
__global__ __launch_bounds__(256, 2) void k_gemm1() {
    __shared__ __align__(16) char sbuf[3][16384];

    int e = blockIdx.z;
    int base = g_off[e], ne = g_off[e + 1] - base;
    int m0 = blockIdx.y * 128;
    if (m0 >= ne) return;
    int n0 = blockIdx.x * 64;

    int tid = threadIdx.x, lane = tid & 31, wid = tid >> 5;
    int wm = wid >> 1, wn = wid & 1;

    size_t wb = ((size_t)e * FF + n0) * DIM;
    const __nv_bfloat16* wgh = g_wgThi + wb;
    const __nv_bfloat16* wgl = g_wgTlo + wb;
    const __nv_bfloat16* wuh = g_wuThi + wb;
    const __nv_bfloat16* wul = g_wuTlo + wb;

    int ar = tid >> 1, aci = tid & 1;
    int arow_ = m0 + ar; if (arow_ >= ne) arow_ = ne - 1;
    size_t tokrow = (size_t)g_tok[base + arow_] * DIM;
    int bh_ = tid >> 7, br = (tid >> 1) & 63, bci = tid & 1;

    // swizzled smem store offsets (gmem offsets keep the un-swizzled column)
    uint32_t sa = ar * 32 + (aci ^ ((ar >> 2) & 1)) * 16;
    uint32_t sB = br * 32 + (bci ^ ((br >> 2) & 1)) * 16;

    uint32_t sb_base = smem_u32(sbuf);
    auto ldstage = [&](int s, int it) {
        uint32_t sb = sb_base + s * 16384;
        int k0 = it * 16;
        cpa16(sb + sa, g_xhi + tokrow + k0 + aci * 8);
        cpa16(sb + 4096 + sa, g_xlo + tokrow + k0 + aci * 8);
        size_t gb = (size_t)br * DIM + k0 + bci * 8;
        cpa16(sb + 8192 + bh_ * 2048 + sB, (bh_ ? wgl : wgh) + gb);
        cpa16(sb + 12288 + bh_ * 2048 + sB, (bh_ ? wul : wuh) + gb);
    };

    float acc_g[2][4][4] = {};
    float acc_u[2][4][4] = {};

    ldstage(0, 0); CPA_COMMIT();
    ldstage(1, 1); CPA_COMMIT();

    const int NIT = DIM / 16;
    // swizzled ldmatrix offsets: col bit XORed with row bit2 (row bits below 16
    // come only from lane, so the XOR term is ((lane>>2)&1))
    uint32_t aoff = (wm * 32 + (lane & 15)) * 32 +
                    (((lane >> 4) ^ ((lane >> 2) & 1)) * 16);
    uint32_t bbase = (wn * 32 + ((lane >> 4) << 3) + (lane & 7)) * 32 +
                     ((((lane >> 3) & 1) ^ ((lane >> 2) & 1)) * 16);

    int s = 0;
    for (int it = 0; it < NIT; it++) {
        CPA_WAIT1();
        __syncthreads();

        if (it + 2 < NIT) ldstage((s + 2 >= 3 ? s - 1 : s + 2), it + 2);
        CPA_COMMIT();

        uint32_t sb = sb_base + s * 16384;
        uint32_t ah[2][4], al[2][4];
        ldm4(ah[0], sb + aoff);
        ldm4(ah[1], sb + aoff + 512);
        ldm4(al[0], sb + 4096 + aoff);
        ldm4(al[1], sb + 4096 + aoff + 512);

#pragma unroll
        for (int half = 0; half < 2; half++) {
            uint32_t bo = bbase + half * 512;
            uint32_t bgh[4], bgl[4], buh[4], bul[4];
            ldm4(bgh, sb + 8192 + bo);
            ldm4(bgl, sb + 10240 + bo);
            ldm4(buh, sb + 12288 + bo);
            ldm4(bul, sb + 14336 + bo);
#pragma unroll
            for (int mt = 0; mt < 2; mt++)
#pragma unroll
                for (int q = 0; q < 2; q++) {
                    int nt = half * 2 + q;
                    mma16816(acc_g[mt][nt], ah[mt], &bgh[q * 2]);
                    mma16816(acc_g[mt][nt], ah[mt], &bgl[q * 2]);
                    mma16816(acc_g[mt][nt], al[mt], &bgh[q * 2]);
                    mma16816(acc_u[mt][nt], ah[mt], &buh[q * 2]);
                    mma16816(acc_u[mt][nt], ah[mt], &bul[q * 2]);
                    mma16816(acc_u[mt][nt], al[mt], &buh[q * 2]);
                }
        }
        s = (s + 1 == 3) ? 0 : s + 1;
    }

#pragma unroll
    for (int mt = 0; mt < 2; mt++)
#pragma unroll
        for (int nt = 0; nt < 4; nt++) {
            int col = n0 + wn * 32 + nt * 8 + 2 * (lane & 3);
#pragma unroll
            for (int rp = 0; rp < 2; rp++) {
                int tr = wm * 32 + mt * 16 + (lane >> 2) + rp * 8;
                if (m0 + tr < ne) {
                    float gg0 = acc_g[mt][nt][rp * 2], gg1 = acc_g[mt][nt][rp * 2 + 1];
                    float uu0 = acc_u[mt][nt][rp * 2], uu1 = acc_u[mt][nt][rp * 2 + 1];
                    float h0 = gg0 / (1.f + __expf(-gg0)) * uu0;
                    float h1 = gg1 / (1.f + __expf(-gg1)) * uu1;
                    __nv_bfloat16 h0h = __float2bfloat16(h0);
                    __nv_bfloat16 h1h = __float2bfloat16(h1);
                    __nv_bfloat16 h0l = __float2bfloat16(h0 - __bfloat162float(h0h));
                    __nv_bfloat16 h1l = __float2bfloat16(h1 - __bfloat162float(h1h));
                    size_t o = (size_t)(base + m0 + tr) * FF + col;
                    *(uint32_t*)(g_hhi + o) = pack2(h0h, h1h);
                    *(uint32_t*)(g_hlo + o) = pack2(h0l, h1l);
                }
            }
        }
}

// ---------------- GEMM2: y = h Wd, bf16x3 HMMA ----------------------------------
__global__ __launch_bounds__(256, 2) void k_gemm2() {
    __shared__ __align__(16) char sbuf[3][12288];

    int e = blockIdx.z;
    int base = g_off[e], ne = g_off[e + 1] - base;
    int m0 = blockIdx.y * 128;
    if (m0 >= ne) return;
    int n0 = blockIdx.x * 64;

    int tid = threadIdx.x, lane = tid & 31, wid = tid >> 5;
    int wm = wid >> 1, wn = wid & 1;

    size_t wb = ((size_t)e * DIM + n0) * FF;
    const __nv_bfloat16* wdh = g_wdThi + wb;
    const __nv_bfloat16* wdl = g_wdTlo + wb;

    int ar = tid >> 1, aci = tid & 1;
    int arr = m0 + ar; if (arr >= ne) arr = ne - 1;
    size_t arow = (size_t)(base + arr) * FF;
    int bh_ = tid >> 7, br = (tid >> 1) & 63, bci = tid & 1;

    uint32_t sa = ar * 32 + (aci ^ ((ar >> 2) & 1)) * 16;
    uint32_t sB = br * 32 + (bci ^ ((br >> 2) & 1)) * 16;

    uint32_t sb_base = smem_u32(sbuf);
    auto ldstage = [&](int s, int it) {
        uint32_t sb = sb_base + s * 12288;
        int k0 = it * 16;
        cpa16(sb + sa, g_hhi + arow + k0 + aci * 8);
        cpa16(sb + 4096 + sa, g_hlo + arow + k0 + aci * 8);
        size_t gb = (size_t)br * FF + k0 + bci * 8;
        cpa16(sb + 8192 + bh_ * 2048 + sB, (bh_ ? wdl : wdh) + gb);
    };

    float acc[2][4][4] = {};

    ldstage(0, 0); CPA_COMMIT();
    ldstage(1, 1); CPA_COMMIT();

    const int NIT = FF / 16;
    uint32_t aoff = (wm * 32 + (lane & 15)) * 32 +
                    (((lane >> 4) ^ ((lane >> 2) & 1)) * 16);
    uint32_t bbase = (wn * 32 + ((lane >> 4) << 3) + (lane & 7)) * 32 +
                     ((((lane >> 3) & 1) ^ ((lane >> 2) & 1)) * 16);

    int s = 0;
    for (int it = 0; it < NIT; it++) {
        CPA_WAIT1();
        __syncthreads();

        if (it + 2 < NIT) ldstage((s + 2 >= 3 ? s - 1 : s + 2), it + 2);
        CPA_COMMIT();

        uint32_t sb = sb_base + s * 12288;
        uint32_t ah[2][4], al[2][4];
        ldm4(ah[0], sb + aoff);
        ldm4(ah[1], sb + aoff + 512);
        ldm4(al[0], sb + 4096 + aoff);
        ldm4(al[1], sb + 4096 + aoff + 512);

#pragma unroll
        for (int half = 0; half < 2; half++) {
            uint32_t bo = bbase + half * 512;
            uint32_t bh4[4], bl4[4];
            ldm4(bh4, sb + 8192 + bo);
            ldm4(bl4, sb + 10240 + bo);
#pragma unroll
            for (int mt = 0; mt < 2; mt++)
#pragma unroll
                for (int q = 0; q < 2; q++) {
                    int nt = half * 2 + q;
                    mma16816(acc[mt][nt], ah[mt], &bh4[q * 2]);
                    mma16816(acc[mt][nt], ah[mt], &bl4[q * 2]);
                    mma16816(acc[mt][nt], al[mt], &bh4[q * 2]);
                }
        }
        s = (s + 1 == 3) ? 0 : s + 1;
    }

#pragma unroll
    for (int mt = 0; mt < 2; mt++)
#pragma unroll
        for (int nt = 0; nt < 4; nt++) {
            int col = n0 + wn * 32 + nt * 8 + 2 * (lane & 3);
#pragma unroll
            for (int rp = 0; rp < 2; rp++) {
                int tr = wm * 32 + mt * 16 + (lane >> 2) + rp * 8;
                if (m0 + tr < ne) {
                    float2* yo = (float2*)(g_y + (size_t)(base + m0 + tr) * DIM + col);
                    *yo = make_float2(acc[mt][nt][rp * 2], acc[mt][nt][rp * 2 + 1]);
                }
            }
        }
}

// ---------------- combine -------------------------------------------------------
__global__ void k_combine(const float* __restrict__ w, float4* __restrict__ out) {
    int i = blockIdx.x * blockDim.x + threadIdx.x;
    int t = i >> 8;
    int d4 = i & 255;
    int p0 = g_pos[2 * t], p1 = g_pos[2 * t + 1];
    float w0 = (p0 < 0) ? 0.f : w[2 * t];
    float w1 = (p1 < 0) ? 0.f : w[2 * t + 1];
    int q0 = p0 < 0 ? 0 : p0, q1 = p1 < 0 ? 0 : p1;
    const float4* y4 = (const float4*)g_y;
    float4 a = y4[(size_t)q0 * 256 + d4];
    float4 b = y4[(size_t)q1 * 256 + d4];
    out[i] = make_float4(w0 * a.x + w1 * b.x, w0 * a.y + w1 * b.y,
                         w0 * a.z + w1 * b.z, w0 * a.w + w1 * b.w);
}

// ---------------- launch --------------------------------------------------------
extern "C" void kernel_launch(void* const* d_in, const int* in_sizes, int n_in,
                              void* d_out, int out_size) {
    const float* x     = (const float*)d_in[0];
    const int*   idx32 = (const int*)d_in[1];
    const float* w     = (const float*)d_in[2];
    const float* wg    = (const float*)d_in[3];
    const float* wu    = (const float*)d_in[4];
    const float* wd    = (const float*)d_in[5];
    float*       out   = (float*)d_out;

    // launch index 3 (k_gemm1) is the one ncu captures — keep it there.
    k_dispatch<<<1, 256>>>(idx32);                                  // 0
    k_cvt_x<<<(TOK * DIM / 4) / 256, 256>>>((const float4*)x);      // 1
    k_cvt_w<<<dim3(32, 32, 48), dim3(32, 8)>>>(wg, wu, wd);         // 2
    k_gemm1<<<dim3(FF / 64, CAP / 128, E_), 256>>>();               // 3  <- profiled
    k_gemm2<<<dim3(DIM / 64, CAP / 128, E_), 256>>>();              // 4
    k_combine<<<(TOK * DIM / 4) / 256, 256>>>(w, (float4*)out);     // 5
}